// round 1
// baseline (speedup 1.0000x reference)
#include <cuda_runtime.h>
#include <cuda_bf16.h>
#include <cstdint>

// Problem constants (fixed by dataset)
constexpr int Nn = 50000;   // nodes
constexpr int Ee = 800000;  // edges
constexpr int Ff = 128;     // feature dim
constexpr int Hh = 256;     // hidden dim
constexpr int Cc = 64;      // classes

// Scratch (device globals: allocation-free per harness rules)
__device__ float g_hprime[(size_t)Nn * Ff];  // dinv*x@W ; later reused as feat
__device__ float g_agg[(size_t)Nn * Ff];     // edge-aggregated
__device__ float g_hh[(size_t)Nn * Hh];      // relu(feat@W_ff+b)
__device__ float g_deg[Nn];                  // degree -> dinv (in place)
__device__ float g_acc[8];                   // [0..2] sum(loss*mask_k), [3..5] sum(mask_k)

// ---------------------------------------------------------------------------
// init: deg = 1 (self loop), accumulators = 0
__global__ void init_k() {
    int i = blockIdx.x * blockDim.x + threadIdx.x;
    if (i < Nn) g_deg[i] = 1.0f;
    if (i < 8) g_acc[i] = 0.0f;
}

// degree count over dst
__global__ void degree_k(const int* __restrict__ adj) {
    int e = blockIdx.x * blockDim.x + threadIdx.x;
    if (e < Ee) atomicAdd(&g_deg[adj[Ee + e]], 1.0f);
}

// deg -> rsqrt(deg) in place
__global__ void rsqrt_k() {
    int i = blockIdx.x * blockDim.x + threadIdx.x;
    if (i < Nn) g_deg[i] = rsqrtf(g_deg[i]);
}

// ---------------------------------------------------------------------------
// Generic 64x64-tile fp32 GEMM, BK=64, 256 threads, 4x4 register tile.
// EPI: 0 = scale rows by dinv, store to C0 and C1 (GCN pre-scale)
//      1 = bias + relu     -> C0
//      2 = bias            -> C0
template <int K, int EPI>
__global__ void gemm64(const float* __restrict__ A, const float* __restrict__ B,
                       const float* __restrict__ bias, float* __restrict__ C0,
                       float* __restrict__ C1, int M, int Ncol) {
    __shared__ float As[64][64];  // [m][k]
    __shared__ float Bs[64][64];  // [k][n]

    const int tid = threadIdx.x;
    const int tx = tid & 15;       // 0..15 -> col group
    const int ty = tid >> 4;       // 0..15 -> row group
    const int m0 = blockIdx.x * 64;
    const int n0 = blockIdx.y * 64;

    float acc[4][4];
#pragma unroll
    for (int i = 0; i < 4; i++)
#pragma unroll
        for (int j = 0; j < 4; j++) acc[i][j] = 0.0f;

    for (int k0 = 0; k0 < K; k0 += 64) {
#pragma unroll
        for (int it = 0; it < 4; it++) {
            int e = tid + it * 256;           // 0..1023 float4 slots
            int r = e >> 4;                    // 0..63
            int c4 = (e & 15) * 4;             // 0..60
            int gr = m0 + r;
            float4 v = make_float4(0.f, 0.f, 0.f, 0.f);
            if (gr < M) v = *(const float4*)(A + (size_t)gr * K + k0 + c4);
            *(float4*)&As[r][c4] = v;
        }
#pragma unroll
        for (int it = 0; it < 4; it++) {
            int e = tid + it * 256;
            int kk = e >> 4;
            int c4 = (e & 15) * 4;
            float4 v = *(const float4*)(B + (size_t)(k0 + kk) * Ncol + n0 + c4);
            *(float4*)&Bs[kk][c4] = v;
        }
        __syncthreads();

#pragma unroll
        for (int kk = 0; kk < 64; kk++) {
            float a0 = As[ty * 4 + 0][kk];
            float a1 = As[ty * 4 + 1][kk];
            float a2 = As[ty * 4 + 2][kk];
            float a3 = As[ty * 4 + 3][kk];
            float4 b = *(const float4*)&Bs[kk][tx * 4];
            acc[0][0] += a0 * b.x; acc[0][1] += a0 * b.y; acc[0][2] += a0 * b.z; acc[0][3] += a0 * b.w;
            acc[1][0] += a1 * b.x; acc[1][1] += a1 * b.y; acc[1][2] += a1 * b.z; acc[1][3] += a1 * b.w;
            acc[2][0] += a2 * b.x; acc[2][1] += a2 * b.y; acc[2][2] += a2 * b.z; acc[2][3] += a2 * b.w;
            acc[3][0] += a3 * b.x; acc[3][1] += a3 * b.y; acc[3][2] += a3 * b.z; acc[3][3] += a3 * b.w;
        }
        __syncthreads();
    }

    float4 bv = make_float4(0.f, 0.f, 0.f, 0.f);
    if (EPI == 1 || EPI == 2) bv = *(const float4*)(bias + n0 + tx * 4);

#pragma unroll
    for (int i = 0; i < 4; i++) {
        int r = m0 + ty * 4 + i;
        if (r >= M) continue;
        float4 v = make_float4(acc[i][0], acc[i][1], acc[i][2], acc[i][3]);
        if (EPI == 0) {
            float s = g_deg[r];  // dinv
            v.x *= s; v.y *= s; v.z *= s; v.w *= s;
            *(float4*)(C0 + (size_t)r * Ncol + n0 + tx * 4) = v;
            *(float4*)(C1 + (size_t)r * Ncol + n0 + tx * 4) = v;
        } else if (EPI == 1) {
            v.x = fmaxf(v.x + bv.x, 0.f); v.y = fmaxf(v.y + bv.y, 0.f);
            v.z = fmaxf(v.z + bv.z, 0.f); v.w = fmaxf(v.w + bv.w, 0.f);
            *(float4*)(C0 + (size_t)r * Ncol + n0 + tx * 4) = v;
        } else {
            v.x += bv.x; v.y += bv.y; v.z += bv.z; v.w += bv.w;
            *(float4*)(C0 + (size_t)r * Ncol + n0 + tx * 4) = v;
        }
    }
}

// ---------------------------------------------------------------------------
// Edge scatter: agg[dst] += hprime[src]. One warp per edge, 4 floats per lane,
// vector reduction (no return value) to global.
__global__ void scatter_k(const int* __restrict__ adj) {
    int eid = blockIdx.x * 8 + (threadIdx.x >> 5);
    int lane = threadIdx.x & 31;
    if (eid >= Ee) return;
    int s = adj[eid];
    int d = adj[Ee + eid];
    float4 v = *(const float4*)(g_hprime + (size_t)s * Ff + lane * 4);
    float* p = g_agg + (size_t)d * Ff + lane * 4;
    asm volatile("red.global.add.v4.f32 [%0], {%1, %2, %3, %4};"
                 :: "l"(p), "f"(v.x), "f"(v.y), "f"(v.z), "f"(v.w)
                 : "memory");
}

// feat[i,k] = dinv[i] * agg[i,k] + b_gcn[k]   (writes into g_hprime, reused)
__global__ void feat_k(const float* __restrict__ b_gcn) {
    int idx = blockIdx.x * blockDim.x + threadIdx.x;  // float4 index
    const int total = Nn * (Ff / 4);
    if (idx >= total) return;
    int row = idx >> 5;            // Ff/4 = 32 float4s per row
    int c4 = (idx & 31) * 4;
    float s = g_deg[row];
    float4 a = *(const float4*)(g_agg + (size_t)row * Ff + c4);
    float4 b = *(const float4*)(b_gcn + c4);
    float4 o;
    o.x = s * a.x + b.x; o.y = s * a.y + b.y;
    o.z = s * a.z + b.z; o.w = s * a.w + b.w;
    *(float4*)(g_hprime + (size_t)row * Ff + c4) = o;
}

// ---------------------------------------------------------------------------
// Per-row log-softmax NLL loss + masked accumulation + logits replication.
// One warp per row (C=64 -> 2 cols per lane). 8 rows per block.
__global__ void loss_k(const int* __restrict__ label, const int* __restrict__ m0,
                       const int* __restrict__ m1, const int* __restrict__ m2,
                       float* __restrict__ out) {
    __shared__ float sa[6];
    int tid = threadIdx.x;
    if (tid < 6) sa[tid] = 0.0f;
    __syncthreads();

    int r = blockIdx.x * 8 + (tid >> 5);
    int lane = tid & 31;
    if (r < Nn) {
        const float* row = out + (size_t)r * Cc;
        float x0 = row[lane];
        float x1 = row[lane + 32];
        // replicate logits into slices 1 and 2
        float* o1 = out + (size_t)Nn * Cc + (size_t)r * Cc;
        float* o2 = o1 + (size_t)Nn * Cc;
        o1[lane] = x0; o1[lane + 32] = x1;
        o2[lane] = x0; o2[lane + 32] = x1;

        float m = fmaxf(x0, x1);
#pragma unroll
        for (int off = 16; off >= 1; off >>= 1)
            m = fmaxf(m, __shfl_xor_sync(0xffffffffu, m, off));
        float se = expf(x0 - m) + expf(x1 - m);
#pragma unroll
        for (int off = 16; off >= 1; off >>= 1)
            se += __shfl_xor_sync(0xffffffffu, se, off);
        float lse = m + logf(se);
        int l = label[r];
        float cand = (l & 32) ? x1 : x0;
        float v = __shfl_sync(0xffffffffu, cand, l & 31);
        float loss = lse - v;
        if (lane == 0) {
            float t0 = (m0[r] == 1) ? 1.0f : 0.0f;
            float t1 = (m1[r] == 1) ? 1.0f : 0.0f;
            float t2 = (m2[r] == 1) ? 1.0f : 0.0f;
            atomicAdd(&sa[0], loss * t0);
            atomicAdd(&sa[1], loss * t1);
            atomicAdd(&sa[2], loss * t2);
            atomicAdd(&sa[3], t0);
            atomicAdd(&sa[4], t1);
            atomicAdd(&sa[5], t2);
        }
    }
    __syncthreads();
    if (tid < 6) atomicAdd(&g_acc[tid], sa[tid]);
}

__global__ void finalize_k(float* __restrict__ out) {
    int k = threadIdx.x;
    if (k < 3) out[(size_t)3 * Nn * Cc + k] = g_acc[k] / g_acc[3 + k];
}

// ---------------------------------------------------------------------------
extern "C" void kernel_launch(void* const* d_in, const int* in_sizes, int n_in,
                              void* d_out, int out_size) {
    const float* feature = (const float*)d_in[0];   // [N,128]
    const int* adj       = (const int*)d_in[1];     // [2,E]
    const int* label     = (const int*)d_in[2];     // [N]
    const int* tmask     = (const int*)d_in[3];
    const int* dmask     = (const int*)d_in[4];
    const int* temask    = (const int*)d_in[5];
    const float* W_gcn   = (const float*)d_in[6];   // [128,128]
    const float* b_gcn   = (const float*)d_in[7];   // [128]
    const float* W_ff    = (const float*)d_in[8];   // [128,256]
    const float* b_ff    = (const float*)d_in[9];   // [256]
    const float* W_pred  = (const float*)d_in[10];  // [256,64]
    const float* b_pred  = (const float*)d_in[11];  // [64]
    float* out = (float*)d_out;

    float* d_hprime; cudaGetSymbolAddress((void**)&d_hprime, g_hprime);
    float* d_agg;    cudaGetSymbolAddress((void**)&d_agg, g_agg);
    float* d_hh;     cudaGetSymbolAddress((void**)&d_hh, g_hh);

    // 1. init + degree + dinv
    init_k<<<(Nn + 255) / 256, 256>>>();
    degree_k<<<(Ee + 255) / 256, 256>>>(adj);
    rsqrt_k<<<(Nn + 255) / 256, 256>>>();

    // 2. hprime = dinv * (feature @ W_gcn); agg = hprime (self loop)
    {
        dim3 grid((Nn + 63) / 64, Ff / 64);
        gemm64<128, 0><<<grid, 256>>>(feature, W_gcn, nullptr, d_hprime, d_agg, Nn, Ff);
    }

    // 3. agg[dst] += hprime[src] over edges
    scatter_k<<<(Ee + 7) / 8, 256>>>(adj);

    // 4. feat = dinv * agg + b_gcn  (into hprime buffer)
    feat_k<<<(Nn * (Ff / 4) + 255) / 256, 256>>>(b_gcn);

    // 5. hh = relu(feat @ W_ff + b_ff)
    {
        dim3 grid((Nn + 63) / 64, Hh / 64);
        gemm64<128, 1><<<grid, 256>>>(d_hprime, W_ff, b_ff, d_hh, nullptr, Nn, Hh);
    }

    // 6. logits = hh @ W_pred + b_pred  -> out slice 0
    {
        dim3 grid((Nn + 63) / 64, Cc / 64);
        gemm64<256, 2><<<grid, 256>>>(d_hh, W_pred, b_pred, out, nullptr, Nn, Cc);
    }

    // 7. loss + copies + masked sums
    loss_k<<<(Nn + 7) / 8, 256>>>(label, tmask, dmask, temask, out);

    // 8. scalars
    finalize_k<<<1, 32>>>(out);
}

// round 2
// speedup vs baseline: 1.0318x; 1.0318x over previous
#include <cuda_runtime.h>
#include <cuda_bf16.h>
#include <cstdint>

// Problem constants (fixed by dataset)
constexpr int Nn = 50000;   // nodes
constexpr int Ee = 800000;  // edges
constexpr int Ff = 128;     // feature dim
constexpr int Hh = 256;     // hidden dim
constexpr int Cc = 64;      // classes

// Scratch (device globals: allocation-free per harness rules)
__device__ float g_hprime[(size_t)Nn * Ff];  // dinv*x@W (scatter source)
__device__ float g_agg[(size_t)Nn * Ff];     // self-loop copy + edge-aggregated
__device__ float g_hh[(size_t)Nn * Hh];      // relu(feat@W_ff+b)
__device__ float g_deg[Nn];                  // degree -> dinv (in place)
__device__ float g_acc[8];                   // [0..2] sum(loss*m_k), [3..5] sum(m_k)

// ---------------------------------------------------------------------------
__global__ void init_k() {
    int i = blockIdx.x * blockDim.x + threadIdx.x;
    if (i < Nn) g_deg[i] = 1.0f;   // self loop
    if (i < 8) g_acc[i] = 0.0f;
}

__global__ void degree_k(const int* __restrict__ adj) {
    int e = blockIdx.x * blockDim.x + threadIdx.x;
    if (e < Ee) atomicAdd(&g_deg[adj[Ee + e]], 1.0f);
}

__global__ void rsqrt_k() {
    int i = blockIdx.x * blockDim.x + threadIdx.x;
    if (i < Nn) g_deg[i] = rsqrtf(g_deg[i]);
}

// ---------------------------------------------------------------------------
// SGEMM: BM=128, BK=32, BN/TN templated, 256 threads, TM=8.
// A staged transposed in smem ([k][m]) so compute-loop A reads are broadcast
// LDS.128. B frags are one LDS.128 per kk.
// AXF: 0 = plain A load
//      1 = A'[r][k] = dinv[r]*A[r][k] + abias[k]   (fused GCN feat transform)
// EPI: 0 = scale rows by dinv, store C0 and C1 (GCN pre-scale + self loop copy)
//      1 = bias + relu -> C0
//      2 = bias        -> C0
template <int K, int BN, int TN, int AXF, int EPI>
__global__ void __launch_bounds__(256, 3)
sgemm(const float* __restrict__ A, const float* __restrict__ B,
      const float* __restrict__ abias, const float* __restrict__ bias,
      float* __restrict__ C0, float* __restrict__ C1, int M, int Ncol) {
    constexpr int BM = 128;
    constexpr int BK = 32;
    __shared__ float As[BK][BM + 4];  // [k][m], pad 4 -> stride 132 (16B aligned)
    __shared__ float Bs[BK][BN];      // [k][n]

    const int tid = threadIdx.x;
    const int tx = tid & 15;   // 0..15 -> n group
    const int ty = tid >> 4;   // 0..15 -> m group
    const int m0 = blockIdx.x * BM;
    const int n0 = blockIdx.y * BN;

    float acc[8][TN];
#pragma unroll
    for (int i = 0; i < 8; i++)
#pragma unroll
        for (int j = 0; j < TN; j++) acc[i][j] = 0.0f;

    for (int k0 = 0; k0 < K; k0 += BK) {
        // --- stage A tile (BM x BK), transposed into As[k][m] ---
#pragma unroll
        for (int it = 0; it < (BM * BK / 4) / 256; it++) {
            int idx = tid + it * 256;       // float4 slot
            int r = idx >> 3;               // 0..127 row within tile
            int q = idx & 7;                // float4 within row (k = q*4)
            int gr = m0 + r;
            float4 v = make_float4(0.f, 0.f, 0.f, 0.f);
            if (gr < M) {
                v = *(const float4*)(A + (size_t)gr * K + k0 + q * 4);
                if (AXF) {
                    float s = g_deg[gr];
                    float4 bb = *(const float4*)(abias + k0 + q * 4);
                    v.x = s * v.x + bb.x; v.y = s * v.y + bb.y;
                    v.z = s * v.z + bb.z; v.w = s * v.w + bb.w;
                }
            }
            As[q * 4 + 0][r] = v.x;
            As[q * 4 + 1][r] = v.y;
            As[q * 4 + 2][r] = v.z;
            As[q * 4 + 3][r] = v.w;
        }
        // --- stage B tile (BK x BN) ---
#pragma unroll
        for (int it = 0; it < (BK * BN / 4) / 256; it++) {
            int idx = tid + it * 256;
            int r = idx / (BN / 4);
            int c4 = (idx % (BN / 4)) * 4;
            *(float4*)&Bs[r][c4] =
                *(const float4*)(B + (size_t)(k0 + r) * Ncol + n0 + c4);
        }
        __syncthreads();

#pragma unroll
        for (int kk = 0; kk < BK; kk++) {
            float4 a0 = *(const float4*)&As[kk][ty * 8];
            float4 a1 = *(const float4*)&As[kk][ty * 8 + 4];
            float a[8] = {a0.x, a0.y, a0.z, a0.w, a1.x, a1.y, a1.z, a1.w};
            float b[TN];
#pragma unroll
            for (int j4 = 0; j4 < TN; j4 += 4) {
                float4 bv = *(const float4*)&Bs[kk][tx * TN + j4];
                b[j4 + 0] = bv.x; b[j4 + 1] = bv.y;
                b[j4 + 2] = bv.z; b[j4 + 3] = bv.w;
            }
#pragma unroll
            for (int i = 0; i < 8; i++)
#pragma unroll
                for (int j = 0; j < TN; j++) acc[i][j] += a[i] * b[j];
        }
        __syncthreads();
    }

    // --- epilogue ---
    float bv[TN];
    if (EPI == 1 || EPI == 2) {
#pragma unroll
        for (int j4 = 0; j4 < TN; j4 += 4) {
            float4 t = *(const float4*)(bias + n0 + tx * TN + j4);
            bv[j4 + 0] = t.x; bv[j4 + 1] = t.y; bv[j4 + 2] = t.z; bv[j4 + 3] = t.w;
        }
    }
#pragma unroll
    for (int i = 0; i < 8; i++) {
        int r = m0 + ty * 8 + i;
        if (r >= M) continue;
        float v[TN];
#pragma unroll
        for (int j = 0; j < TN; j++) v[j] = acc[i][j];
        if (EPI == 0) {
            float s = g_deg[r];
#pragma unroll
            for (int j = 0; j < TN; j++) v[j] *= s;
        } else if (EPI == 1) {
#pragma unroll
            for (int j = 0; j < TN; j++) v[j] = fmaxf(v[j] + bv[j], 0.f);
        } else {
#pragma unroll
            for (int j = 0; j < TN; j++) v[j] += bv[j];
        }
#pragma unroll
        for (int j4 = 0; j4 < TN; j4 += 4) {
            float4 t = make_float4(v[j4], v[j4 + 1], v[j4 + 2], v[j4 + 3]);
            *(float4*)(C0 + (size_t)r * Ncol + n0 + tx * TN + j4) = t;
            if (EPI == 0)
                *(float4*)(C1 + (size_t)r * Ncol + n0 + tx * TN + j4) = t;
        }
    }
}

// ---------------------------------------------------------------------------
// Edge scatter: agg[dst] += hprime[src]. One warp per edge, float4 per lane.
__global__ void scatter_k(const int* __restrict__ adj) {
    int eid = blockIdx.x * 8 + (threadIdx.x >> 5);
    int lane = threadIdx.x & 31;
    if (eid >= Ee) return;
    int s = adj[eid];
    int d = adj[Ee + eid];
    float4 v = *(const float4*)(g_hprime + (size_t)s * Ff + lane * 4);
    float* p = g_agg + (size_t)d * Ff + lane * 4;
    asm volatile("red.global.add.v4.f32 [%0], {%1, %2, %3, %4};"
                 :: "l"(p), "f"(v.x), "f"(v.y), "f"(v.z), "f"(v.w)
                 : "memory");
}

// ---------------------------------------------------------------------------
// Per-row log-softmax NLL loss + masked accumulation + logits replication.
__global__ void loss_k(const int* __restrict__ label, const int* __restrict__ m0,
                       const int* __restrict__ m1, const int* __restrict__ m2,
                       float* __restrict__ out) {
    __shared__ float sa[6];
    int tid = threadIdx.x;
    if (tid < 6) sa[tid] = 0.0f;
    __syncthreads();

    int r = blockIdx.x * 8 + (tid >> 5);
    int lane = tid & 31;
    if (r < Nn) {
        const float* row = out + (size_t)r * Cc;
        float x0 = row[lane];
        float x1 = row[lane + 32];
        float* o1 = out + (size_t)Nn * Cc + (size_t)r * Cc;
        float* o2 = o1 + (size_t)Nn * Cc;
        o1[lane] = x0; o1[lane + 32] = x1;
        o2[lane] = x0; o2[lane + 32] = x1;

        float m = fmaxf(x0, x1);
#pragma unroll
        for (int off = 16; off >= 1; off >>= 1)
            m = fmaxf(m, __shfl_xor_sync(0xffffffffu, m, off));
        float se = expf(x0 - m) + expf(x1 - m);
#pragma unroll
        for (int off = 16; off >= 1; off >>= 1)
            se += __shfl_xor_sync(0xffffffffu, se, off);
        float lse = m + logf(se);
        int l = label[r];
        float cand = (l & 32) ? x1 : x0;
        float v = __shfl_sync(0xffffffffu, cand, l & 31);
        float loss = lse - v;
        if (lane == 0) {
            float t0 = (m0[r] == 1) ? 1.0f : 0.0f;
            float t1 = (m1[r] == 1) ? 1.0f : 0.0f;
            float t2 = (m2[r] == 1) ? 1.0f : 0.0f;
            atomicAdd(&sa[0], loss * t0);
            atomicAdd(&sa[1], loss * t1);
            atomicAdd(&sa[2], loss * t2);
            atomicAdd(&sa[3], t0);
            atomicAdd(&sa[4], t1);
            atomicAdd(&sa[5], t2);
        }
    }
    __syncthreads();
    if (tid < 6) atomicAdd(&g_acc[tid], sa[tid]);
}

__global__ void finalize_k(float* __restrict__ out) {
    int k = threadIdx.x;
    if (k < 3) out[(size_t)3 * Nn * Cc + k] = g_acc[k] / g_acc[3 + k];
}

// ---------------------------------------------------------------------------
extern "C" void kernel_launch(void* const* d_in, const int* in_sizes, int n_in,
                              void* d_out, int out_size) {
    const float* feature = (const float*)d_in[0];   // [N,128]
    const int* adj       = (const int*)d_in[1];     // [2,E]
    const int* label     = (const int*)d_in[2];     // [N]
    const int* tmask     = (const int*)d_in[3];
    const int* dmask     = (const int*)d_in[4];
    const int* temask    = (const int*)d_in[5];
    const float* W_gcn   = (const float*)d_in[6];   // [128,128]
    const float* b_gcn   = (const float*)d_in[7];   // [128]
    const float* W_ff    = (const float*)d_in[8];   // [128,256]
    const float* b_ff    = (const float*)d_in[9];   // [256]
    const float* W_pred  = (const float*)d_in[10];  // [256,64]
    const float* b_pred  = (const float*)d_in[11];  // [64]
    float* out = (float*)d_out;

    float* d_hprime; cudaGetSymbolAddress((void**)&d_hprime, g_hprime);
    float* d_agg;    cudaGetSymbolAddress((void**)&d_agg, g_agg);
    float* d_hh;     cudaGetSymbolAddress((void**)&d_hh, g_hh);

    const int MB = (Nn + 127) / 128;  // 391

    // 1. degrees -> dinv
    init_k<<<(Nn + 255) / 256, 256>>>();
    degree_k<<<(Ee + 255) / 256, 256>>>(adj);
    rsqrt_k<<<(Nn + 255) / 256, 256>>>();

    // 2. hprime = dinv * (feature @ W_gcn); agg = hprime (self loop)
    {
        dim3 grid(MB, Ff / 64);
        sgemm<128, 64, 4, 0, 0><<<grid, 256>>>(feature, W_gcn, nullptr, nullptr,
                                               d_hprime, d_agg, Nn, Ff);
    }

    // 3. agg[dst] += hprime[src] over edges
    scatter_k<<<(Ee + 7) / 8, 256>>>(adj);

    // 4+5. hh = relu((dinv*agg + b_gcn) @ W_ff + b_ff)   [feat fused into A-load]
    {
        dim3 grid(MB, Hh / 64);
        sgemm<128, 64, 4, 1, 1><<<grid, 256>>>(d_agg, W_ff, b_gcn, b_ff,
                                               d_hh, nullptr, Nn, Hh);
    }

    // 6. logits = hh @ W_pred + b_pred  -> out slice 0
    {
        dim3 grid(MB, Cc / 64);
        sgemm<256, 64, 4, 0, 2><<<grid, 256>>>(d_hh, W_pred, nullptr, b_pred,
                                               out, nullptr, Nn, Cc);
    }

    // 7. loss + copies + masked sums
    loss_k<<<(Nn + 7) / 8, 256>>>(label, tmask, dmask, temask, out);

    // 8. scalars
    finalize_k<<<1, 32>>>(out);
}

// round 4
// speedup vs baseline: 1.3618x; 1.3198x over previous
#include <cuda_runtime.h>
#include <cuda_bf16.h>
#include <cstdint>

// Problem constants
constexpr int Nn = 50000;
constexpr int Ee = 800000;
constexpr int Ff = 128;
constexpr int Hh = 256;
constexpr int Cc = 64;

// Scratch
__device__ float g_hprime[(size_t)Nn * Ff];
__device__ float g_agg[(size_t)Nn * Ff];
__device__ float g_hh[(size_t)Nn * Hh];
__device__ float g_deg[Nn];
__device__ float g_acc[8];

// ---------------------------------------------------------------------------
__global__ void init_k() {
    int i = blockIdx.x * blockDim.x + threadIdx.x;
    if (i < Nn) g_deg[i] = 1.0f;
    if (i < 8) g_acc[i] = 0.0f;
}
__global__ void degree_k(const int* __restrict__ adj) {
    int e = blockIdx.x * blockDim.x + threadIdx.x;
    if (e < Ee) atomicAdd(&g_deg[adj[Ee + e]], 1.0f);
}
__global__ void rsqrt_k() {
    int i = blockIdx.x * blockDim.x + threadIdx.x;
    if (i < Nn) g_deg[i] = rsqrtf(g_deg[i]);
}

// ---------------------------------------------------------------------------
__device__ __forceinline__ uint32_t smem_u32(const void* p) {
    uint32_t a;
    asm("{ .reg .u64 t; cvta.to.shared.u64 t, %1; cvt.u32.u64 %0, t; }"
        : "=r"(a) : "l"(p));
    return a;
}
__device__ __forceinline__ void ldsm_x4(uint32_t* r, uint32_t addr) {
    asm volatile("ldmatrix.sync.aligned.m8n8.x4.shared.b16 {%0,%1,%2,%3}, [%4];"
                 : "=r"(r[0]), "=r"(r[1]), "=r"(r[2]), "=r"(r[3]) : "r"(addr));
}
__device__ __forceinline__ void ldsm_x2t(uint32_t* r, uint32_t addr) {
    asm volatile("ldmatrix.sync.aligned.m8n8.x2.trans.shared.b16 {%0,%1}, [%2];"
                 : "=r"(r[0]), "=r"(r[1]) : "r"(addr));
}
__device__ __forceinline__ void mma_bf16(float* d, const uint32_t* a, const uint32_t* b) {
    asm volatile(
        "mma.sync.aligned.m16n8k16.row.col.f32.bf16.bf16.f32 "
        "{%0,%1,%2,%3}, {%4,%5,%6,%7}, {%8,%9}, {%0,%1,%2,%3};"
        : "+f"(d[0]), "+f"(d[1]), "+f"(d[2]), "+f"(d[3])
        : "r"(a[0]), "r"(a[1]), "r"(a[2]), "r"(a[3]), "r"(b[0]), "r"(b[1]));
}
__device__ __forceinline__ void split_bf16(float x, __nv_bfloat16& h, __nv_bfloat16& l) {
    h = __float2bfloat16(x);
    l = __float2bfloat16(x - __bfloat162float(h));
}

// ---------------------------------------------------------------------------
// HMMA bf16-split GEMM: C[M,Ncol] = A[M,K] @ B[K,Ncol] (+epi)
// BM=128, BN=64, BK=32. 256 threads = 8 warps (4 m x 2 n), warp tile 32x32.
// AXF: 1 -> A'[r][k] = dinv[r]*A[r][k] + abias[k]
// EPI: 0 -> v*=dinv[r], store C0,C1 ; 1 -> relu(v+bias)->C0 ; 2 -> v+bias->C0
template <int K, int AXF, int EPI>
__global__ void __launch_bounds__(256)
mmagemm(const float* __restrict__ A, const float* __restrict__ B,
        const float* __restrict__ abias, const float* __restrict__ bias,
        float* __restrict__ C0, float* __restrict__ C1, int M, int Ncol) {
    constexpr int ASTR = 40;  // bf16 elems per A smem row (80B, 16B-aligned)
    constexpr int BSTR = 72;  // bf16 elems per B smem row (144B, 16B-aligned)
    __shared__ __align__(16) __nv_bfloat16 Ash[128 * ASTR];
    __shared__ __align__(16) __nv_bfloat16 Asl[128 * ASTR];
    __shared__ __align__(16) __nv_bfloat16 Bsh[32 * BSTR];
    __shared__ __align__(16) __nv_bfloat16 Bsl[32 * BSTR];

    const int tid = threadIdx.x;
    const int wid = tid >> 5;
    const int lane = tid & 31;
    const int wm = wid & 3;        // 0..3 (m)
    const int wn = wid >> 2;       // 0..1 (n)
    const int m0 = blockIdx.x * 128;
    const int n0 = blockIdx.y * 64;

    const uint32_t uAsh = smem_u32(Ash), uAsl = smem_u32(Asl);
    const uint32_t uBsh = smem_u32(Bsh), uBsl = smem_u32(Bsl);

    // ldmatrix address bases (bytes)
    const int l15 = lane & 15;
    const int lh = lane >> 4;  // 0/1 -> k half for A
    // A: row = wm*32 + mi*16 + l15 ; col = ks*16 + lh*8
    uint32_t aBase[2], alBase[2];
#pragma unroll
    for (int mi = 0; mi < 2; mi++) {
        uint32_t off = (uint32_t)((wm * 32 + mi * 16 + l15) * (ASTR * 2) + lh * 16);
        aBase[mi] = uAsh + off;
        alBase[mi] = uAsl + off;
    }
    // B: krow = ks*16 + l15 ; col = wn*32 + ni*8
    uint32_t bBase = (uint32_t)(l15 * (BSTR * 2) + wn * 64);

    float acc[2][4][4];
#pragma unroll
    for (int mi = 0; mi < 2; mi++)
#pragma unroll
        for (int ni = 0; ni < 4; ni++)
#pragma unroll
            for (int j = 0; j < 4; j++) acc[mi][ni][j] = 0.0f;

    constexpr int NC = K / 32;
#pragma unroll 1
    for (int c = 0; c < NC; c++) {
        const int k0 = c * 32;
        if (c > 0) __syncthreads();  // protect prev-iter reads
        // ---- stage A tile (128 x 32 fp32 -> bf16 hi/lo) ----
#pragma unroll
        for (int it = 0; it < 4; it++) {
            int idx = it * 256 + tid;
            int r = idx >> 3;
            int q = idx & 7;
            int gr = m0 + r;
            float4 v = make_float4(0.f, 0.f, 0.f, 0.f);
            if (gr < M) {
                v = *(const float4*)(A + (size_t)gr * K + k0 + q * 4);
                if (AXF) {
                    float sc = g_deg[gr];
                    float4 bb = *(const float4*)(abias + k0 + q * 4);
                    v.x = sc * v.x + bb.x; v.y = sc * v.y + bb.y;
                    v.z = sc * v.z + bb.z; v.w = sc * v.w + bb.w;
                }
            }
            __nv_bfloat16 hx, lx, hy, ly, hz, lz, hw, lw;
            split_bf16(v.x, hx, lx); split_bf16(v.y, hy, ly);
            split_bf16(v.z, hz, lz); split_bf16(v.w, hw, lw);
            int e = r * ASTR + q * 4;
            *(__nv_bfloat162*)&Ash[e]     = __nv_bfloat162(hx, hy);
            *(__nv_bfloat162*)&Ash[e + 2] = __nv_bfloat162(hz, hw);
            *(__nv_bfloat162*)&Asl[e]     = __nv_bfloat162(lx, ly);
            *(__nv_bfloat162*)&Asl[e + 2] = __nv_bfloat162(lz, lw);
        }
        // ---- stage B tile (32 x 64 fp32 -> bf16 hi/lo) ----
#pragma unroll
        for (int it = 0; it < 2; it++) {
            int idx = it * 256 + tid;
            int k = idx >> 4;
            int n4 = (idx & 15) * 4;
            float4 v = *(const float4*)(B + (size_t)(k0 + k) * Ncol + n0 + n4);
            __nv_bfloat16 hx, lx, hy, ly, hz, lz, hw, lw;
            split_bf16(v.x, hx, lx); split_bf16(v.y, hy, ly);
            split_bf16(v.z, hz, lz); split_bf16(v.w, hw, lw);
            int e = k * BSTR + n4;
            *(__nv_bfloat162*)&Bsh[e]     = __nv_bfloat162(hx, hy);
            *(__nv_bfloat162*)&Bsh[e + 2] = __nv_bfloat162(hz, hw);
            *(__nv_bfloat162*)&Bsl[e]     = __nv_bfloat162(lx, ly);
            *(__nv_bfloat162*)&Bsl[e + 2] = __nv_bfloat162(lz, lw);
        }
        __syncthreads();

        // ---- compute: 2 k16 steps ----
#pragma unroll
        for (int ks = 0; ks < 2; ks++) {
            uint32_t ah[2][4], al[2][4], bh[4][2], bl[4][2];
#pragma unroll
            for (int mi = 0; mi < 2; mi++) {
                ldsm_x4(ah[mi], aBase[mi] + ks * 32);
                ldsm_x4(al[mi], alBase[mi] + ks * 32);
            }
#pragma unroll
            for (int ni = 0; ni < 4; ni++) {
                uint32_t boff = bBase + ks * 16 * (BSTR * 2) + ni * 16;
                ldsm_x2t(bh[ni], uBsh + boff);
                ldsm_x2t(bl[ni], uBsl + boff);
            }
#pragma unroll
            for (int mi = 0; mi < 2; mi++)
#pragma unroll
                for (int ni = 0; ni < 4; ni++) {
                    mma_bf16(acc[mi][ni], ah[mi], bh[ni]);
                    mma_bf16(acc[mi][ni], ah[mi], bl[ni]);
                    mma_bf16(acc[mi][ni], al[mi], bh[ni]);
                }
        }
    }

    // ---- epilogue ----
    const int g = lane >> 2;
    const int tig = lane & 3;
#pragma unroll
    for (int mi = 0; mi < 2; mi++) {
        int row0 = m0 + wm * 32 + mi * 16 + g;
        int row1 = row0 + 8;
        float s0 = 1.f, s1 = 1.f;
        if (EPI == 0) {
            if (row0 < M) s0 = g_deg[row0];
            if (row1 < M) s1 = g_deg[row1];
        }
#pragma unroll
        for (int ni = 0; ni < 4; ni++) {
            int col = n0 + wn * 32 + ni * 8 + tig * 2;
            float v0 = acc[mi][ni][0], v1 = acc[mi][ni][1];
            float v2 = acc[mi][ni][2], v3 = acc[mi][ni][3];
            if (EPI == 0) {
                v0 *= s0; v1 *= s0; v2 *= s1; v3 *= s1;
            } else {
                float2 b = *(const float2*)(bias + col);
                v0 += b.x; v1 += b.y; v2 += b.x; v3 += b.y;
                if (EPI == 1) {
                    v0 = fmaxf(v0, 0.f); v1 = fmaxf(v1, 0.f);
                    v2 = fmaxf(v2, 0.f); v3 = fmaxf(v3, 0.f);
                }
            }
            if (row0 < M) {
                *(float2*)(C0 + (size_t)row0 * Ncol + col) = make_float2(v0, v1);
                if (EPI == 0)
                    *(float2*)(C1 + (size_t)row0 * Ncol + col) = make_float2(v0, v1);
            }
            if (row1 < M) {
                *(float2*)(C0 + (size_t)row1 * Ncol + col) = make_float2(v2, v3);
                if (EPI == 0)
                    *(float2*)(C1 + (size_t)row1 * Ncol + col) = make_float2(v2, v3);
            }
        }
    }
}

// ---------------------------------------------------------------------------
__global__ void scatter_k(const int* __restrict__ adj) {
    int eid = blockIdx.x * 8 + (threadIdx.x >> 5);
    int lane = threadIdx.x & 31;
    if (eid >= Ee) return;
    int s = adj[eid];
    int d = adj[Ee + eid];
    float4 v = *(const float4*)(g_hprime + (size_t)s * Ff + lane * 4);
    float* p = g_agg + (size_t)d * Ff + lane * 4;
    asm volatile("red.global.add.v4.f32 [%0], {%1, %2, %3, %4};"
                 :: "l"(p), "f"(v.x), "f"(v.y), "f"(v.z), "f"(v.w)
                 : "memory");
}

// ---------------------------------------------------------------------------
__global__ void loss_k(const int* __restrict__ label, const int* __restrict__ m0,
                       const int* __restrict__ m1, const int* __restrict__ m2,
                       float* __restrict__ out) {
    __shared__ float sa[6];
    int tid = threadIdx.x;
    if (tid < 6) sa[tid] = 0.0f;
    __syncthreads();

    int r = blockIdx.x * 8 + (tid >> 5);
    int lane = tid & 31;
    if (r < Nn) {
        const float* row = out + (size_t)r * Cc;
        float x0 = row[lane];
        float x1 = row[lane + 32];
        float* o1 = out + (size_t)Nn * Cc + (size_t)r * Cc;
        float* o2 = o1 + (size_t)Nn * Cc;
        o1[lane] = x0; o1[lane + 32] = x1;
        o2[lane] = x0; o2[lane + 32] = x1;

        float m = fmaxf(x0, x1);
#pragma unroll
        for (int off = 16; off >= 1; off >>= 1)
            m = fmaxf(m, __shfl_xor_sync(0xffffffffu, m, off));
        float se = expf(x0 - m) + expf(x1 - m);
#pragma unroll
        for (int off = 16; off >= 1; off >>= 1)
            se += __shfl_xor_sync(0xffffffffu, se, off);
        float lse = m + logf(se);
        int l = label[r];
        float cand = (l & 32) ? x1 : x0;
        float v = __shfl_sync(0xffffffffu, cand, l & 31);
        float loss = lse - v;
        if (lane == 0) {
            float t0 = (m0[r] == 1) ? 1.0f : 0.0f;
            float t1 = (m1[r] == 1) ? 1.0f : 0.0f;
            float t2 = (m2[r] == 1) ? 1.0f : 0.0f;
            atomicAdd(&sa[0], loss * t0);
            atomicAdd(&sa[1], loss * t1);
            atomicAdd(&sa[2], loss * t2);
            atomicAdd(&sa[3], t0);
            atomicAdd(&sa[4], t1);
            atomicAdd(&sa[5], t2);
        }
    }
    __syncthreads();
    if (tid < 6) atomicAdd(&g_acc[tid], sa[tid]);
}

__global__ void finalize_k(float* __restrict__ out) {
    int k = threadIdx.x;
    if (k < 3) out[(size_t)3 * Nn * Cc + k] = g_acc[k] / g_acc[3 + k];
}

// ---------------------------------------------------------------------------
extern "C" void kernel_launch(void* const* d_in, const int* in_sizes, int n_in,
                              void* d_out, int out_size) {
    const float* feature = (const float*)d_in[0];
    const int* adj       = (const int*)d_in[1];
    const int* label     = (const int*)d_in[2];
    const int* tmask     = (const int*)d_in[3];
    const int* dmask     = (const int*)d_in[4];
    const int* temask    = (const int*)d_in[5];
    const float* W_gcn   = (const float*)d_in[6];
    const float* b_gcn   = (const float*)d_in[7];
    const float* W_ff    = (const float*)d_in[8];
    const float* b_ff    = (const float*)d_in[9];
    const float* W_pred  = (const float*)d_in[10];
    const float* b_pred  = (const float*)d_in[11];
    float* out = (float*)d_out;

    float* d_hprime; cudaGetSymbolAddress((void**)&d_hprime, g_hprime);
    float* d_agg;    cudaGetSymbolAddress((void**)&d_agg, g_agg);
    float* d_hh;     cudaGetSymbolAddress((void**)&d_hh, g_hh);

    const int MB = (Nn + 127) / 128;  // 391

    // 1. degrees -> dinv
    init_k<<<(Nn + 255) / 256, 256>>>();
    degree_k<<<(Ee + 255) / 256, 256>>>(adj);
    rsqrt_k<<<(Nn + 255) / 256, 256>>>();

    // 2. hprime = dinv * (feature @ W_gcn); agg = hprime (self loop)
    {
        dim3 grid(MB, Ff / 64);
        mmagemm<128, 0, 0><<<grid, 256>>>(feature, W_gcn, nullptr, nullptr,
                                          d_hprime, d_agg, Nn, Ff);
    }

    // 3. agg[dst] += hprime[src]
    scatter_k<<<(Ee + 7) / 8, 256>>>(adj);

    // 4+5. hh = relu((dinv*agg + b_gcn) @ W_ff + b_ff)
    {
        dim3 grid(MB, Hh / 64);
        mmagemm<128, 1, 1><<<grid, 256>>>(d_agg, W_ff, b_gcn, b_ff,
                                          d_hh, nullptr, Nn, Hh);
    }

    // 6. logits = hh @ W_pred + b_pred
    {
        dim3 grid(MB, Cc / 64);
        mmagemm<256, 0, 2><<<grid, 256>>>(d_hh, W_pred, nullptr, b_pred,
                                          out, nullptr, Nn, Cc);
    }

    // 7. loss + copies + masked sums
    loss_k<<<(Nn + 7) / 8, 256>>>(label, tmask, dmask, temask, out);

    // 8. scalars
    finalize_k<<<1, 32>>>(out);
}

// round 5
// speedup vs baseline: 1.7431x; 1.2800x over previous
#include <cuda_runtime.h>
#include <cuda_bf16.h>
#include <cstdint>

// Problem constants
constexpr int Nn = 50000;
constexpr int Ee = 800000;
constexpr int Ff = 128;
constexpr int Hh = 256;
constexpr int Cc = 64;

constexpr int SCAN_B = 512;
constexpr int NBLK = (Nn + SCAN_B - 1) / SCAN_B;  // 98

// Scratch
__device__ float g_hprime[(size_t)Nn * Ff];
__device__ float g_agg[(size_t)Nn * Ff];
__device__ float g_hh[(size_t)Nn * Hh];
__device__ float g_deg[Nn];     // dinv
__device__ float g_acc[8];
__device__ int g_cnt[Nn];       // in-degree (no self loop)
__device__ int g_fill[Nn];      // fill cursors
__device__ int g_rowptr[Nn];    // CSR row starts
__device__ int g_bsum[NBLK];    // scan block sums
__device__ int g_esrc[Ee];      // CSR src indices (grouped by dst)

// ---------------------------------------------------------------------------
__global__ void init_k() {
    int i = blockIdx.x * blockDim.x + threadIdx.x;
    if (i < Nn) { g_cnt[i] = 0; g_fill[i] = 0; }
    if (i < 8) g_acc[i] = 0.0f;
}
__global__ void cnt_k(const int* __restrict__ adj) {
    int e = blockIdx.x * blockDim.x + threadIdx.x;
    if (e < Ee) atomicAdd(&g_cnt[adj[Ee + e]], 1);
}
// block-local exclusive scan of g_cnt (512/block) + block totals + dinv
__global__ void scan1_k() {
    __shared__ int s[SCAN_B];
    int tid = threadIdx.x;
    int i = blockIdx.x * SCAN_B + tid;
    int v = (i < Nn) ? g_cnt[i] : 0;
    s[tid] = v;
    __syncthreads();
#pragma unroll
    for (int off = 1; off < SCAN_B; off <<= 1) {
        int t = (tid >= off) ? s[tid - off] : 0;
        __syncthreads();
        s[tid] += t;
        __syncthreads();
    }
    if (i < Nn) {
        g_rowptr[i] = s[tid] - v;
        g_deg[i] = rsqrtf((float)(v + 1));
    }
    if (tid == SCAN_B - 1) g_bsum[blockIdx.x] = s[tid];
}
__global__ void scan2_k() {
    __shared__ int s[128];
    int tid = threadIdx.x;
    if (tid < NBLK) s[tid] = g_bsum[tid];
    __syncthreads();
    if (tid == 0) {
        int run = 0;
        for (int i = 0; i < NBLK; i++) { int t = s[i]; s[i] = run; run += t; }
    }
    __syncthreads();
    if (tid < NBLK) g_bsum[tid] = s[tid];
}
__global__ void scan3_k() {
    int i = blockIdx.x * blockDim.x + threadIdx.x;
    if (i < Nn) g_rowptr[i] += g_bsum[i >> 9];
}
__global__ void fill_k(const int* __restrict__ adj) {
    int e = blockIdx.x * blockDim.x + threadIdx.x;
    if (e >= Ee) return;
    int src = adj[e];
    int dst = adj[Ee + e];
    int pos = g_rowptr[dst] + atomicAdd(&g_fill[dst], 1);
    g_esrc[pos] = src;
}

// ---------------------------------------------------------------------------
__device__ __forceinline__ uint32_t smem_u32(const void* p) {
    uint32_t a;
    asm("{ .reg .u64 t; cvta.to.shared.u64 t, %1; cvt.u32.u64 %0, t; }"
        : "=r"(a) : "l"(p));
    return a;
}
__device__ __forceinline__ void ldsm_x4(uint32_t* r, uint32_t addr) {
    asm volatile("ldmatrix.sync.aligned.m8n8.x4.shared.b16 {%0,%1,%2,%3}, [%4];"
                 : "=r"(r[0]), "=r"(r[1]), "=r"(r[2]), "=r"(r[3]) : "r"(addr));
}
__device__ __forceinline__ void ldsm_x2t(uint32_t* r, uint32_t addr) {
    asm volatile("ldmatrix.sync.aligned.m8n8.x2.trans.shared.b16 {%0,%1}, [%2];"
                 : "=r"(r[0]), "=r"(r[1]) : "r"(addr));
}
__device__ __forceinline__ void mma_bf16(float* d, const uint32_t* a, const uint32_t* b) {
    asm volatile(
        "mma.sync.aligned.m16n8k16.row.col.f32.bf16.bf16.f32 "
        "{%0,%1,%2,%3}, {%4,%5,%6,%7}, {%8,%9}, {%0,%1,%2,%3};"
        : "+f"(d[0]), "+f"(d[1]), "+f"(d[2]), "+f"(d[3])
        : "r"(a[0]), "r"(a[1]), "r"(a[2]), "r"(a[3]), "r"(b[0]), "r"(b[1]));
}
__device__ __forceinline__ void split_bf16(float x, __nv_bfloat16& h, __nv_bfloat16& l) {
    h = __float2bfloat16(x);
    l = __float2bfloat16(x - __bfloat162float(h));
}

// ---------------------------------------------------------------------------
// HMMA bf16-split GEMM (same as R4, EPI 0 no longer writes C1)
template <int K, int AXF, int EPI>
__global__ void __launch_bounds__(256)
mmagemm(const float* __restrict__ A, const float* __restrict__ B,
        const float* __restrict__ abias, const float* __restrict__ bias,
        float* __restrict__ C0, int M, int Ncol) {
    constexpr int ASTR = 40;
    constexpr int BSTR = 72;
    __shared__ __align__(16) __nv_bfloat16 Ash[128 * ASTR];
    __shared__ __align__(16) __nv_bfloat16 Asl[128 * ASTR];
    __shared__ __align__(16) __nv_bfloat16 Bsh[32 * BSTR];
    __shared__ __align__(16) __nv_bfloat16 Bsl[32 * BSTR];

    const int tid = threadIdx.x;
    const int wid = tid >> 5;
    const int lane = tid & 31;
    const int wm = wid & 3;
    const int wn = wid >> 2;
    const int m0 = blockIdx.x * 128;
    const int n0 = blockIdx.y * 64;

    const uint32_t uAsh = smem_u32(Ash), uAsl = smem_u32(Asl);
    const uint32_t uBsh = smem_u32(Bsh), uBsl = smem_u32(Bsl);

    const int l15 = lane & 15;
    const int lh = lane >> 4;
    uint32_t aBase[2], alBase[2];
#pragma unroll
    for (int mi = 0; mi < 2; mi++) {
        uint32_t off = (uint32_t)((wm * 32 + mi * 16 + l15) * (ASTR * 2) + lh * 16);
        aBase[mi] = uAsh + off;
        alBase[mi] = uAsl + off;
    }
    uint32_t bBase = (uint32_t)(l15 * (BSTR * 2) + wn * 64);

    float acc[2][4][4];
#pragma unroll
    for (int mi = 0; mi < 2; mi++)
#pragma unroll
        for (int ni = 0; ni < 4; ni++)
#pragma unroll
            for (int j = 0; j < 4; j++) acc[mi][ni][j] = 0.0f;

    constexpr int NC = K / 32;
#pragma unroll 1
    for (int c = 0; c < NC; c++) {
        const int k0 = c * 32;
        if (c > 0) __syncthreads();
#pragma unroll
        for (int it = 0; it < 4; it++) {
            int idx = it * 256 + tid;
            int r = idx >> 3;
            int q = idx & 7;
            int gr = m0 + r;
            float4 v = make_float4(0.f, 0.f, 0.f, 0.f);
            if (gr < M) {
                v = *(const float4*)(A + (size_t)gr * K + k0 + q * 4);
                if (AXF) {
                    float sc = g_deg[gr];
                    float4 bb = *(const float4*)(abias + k0 + q * 4);
                    v.x = sc * v.x + bb.x; v.y = sc * v.y + bb.y;
                    v.z = sc * v.z + bb.z; v.w = sc * v.w + bb.w;
                }
            }
            __nv_bfloat16 hx, lx, hy, ly, hz, lz, hw, lw;
            split_bf16(v.x, hx, lx); split_bf16(v.y, hy, ly);
            split_bf16(v.z, hz, lz); split_bf16(v.w, hw, lw);
            int e = r * ASTR + q * 4;
            *(__nv_bfloat162*)&Ash[e]     = __nv_bfloat162(hx, hy);
            *(__nv_bfloat162*)&Ash[e + 2] = __nv_bfloat162(hz, hw);
            *(__nv_bfloat162*)&Asl[e]     = __nv_bfloat162(lx, ly);
            *(__nv_bfloat162*)&Asl[e + 2] = __nv_bfloat162(lz, lw);
        }
#pragma unroll
        for (int it = 0; it < 2; it++) {
            int idx = it * 256 + tid;
            int k = idx >> 4;
            int n4 = (idx & 15) * 4;
            float4 v = *(const float4*)(B + (size_t)(k0 + k) * Ncol + n0 + n4);
            __nv_bfloat16 hx, lx, hy, ly, hz, lz, hw, lw;
            split_bf16(v.x, hx, lx); split_bf16(v.y, hy, ly);
            split_bf16(v.z, hz, lz); split_bf16(v.w, hw, lw);
            int e = k * BSTR + n4;
            *(__nv_bfloat162*)&Bsh[e]     = __nv_bfloat162(hx, hy);
            *(__nv_bfloat162*)&Bsh[e + 2] = __nv_bfloat162(hz, hw);
            *(__nv_bfloat162*)&Bsl[e]     = __nv_bfloat162(lx, ly);
            *(__nv_bfloat162*)&Bsl[e + 2] = __nv_bfloat162(lz, lw);
        }
        __syncthreads();

#pragma unroll
        for (int ks = 0; ks < 2; ks++) {
            uint32_t ah[2][4], al[2][4], bh[4][2], bl[4][2];
#pragma unroll
            for (int mi = 0; mi < 2; mi++) {
                ldsm_x4(ah[mi], aBase[mi] + ks * 32);
                ldsm_x4(al[mi], alBase[mi] + ks * 32);
            }
#pragma unroll
            for (int ni = 0; ni < 4; ni++) {
                uint32_t boff = bBase + ks * 16 * (BSTR * 2) + ni * 16;
                ldsm_x2t(bh[ni], uBsh + boff);
                ldsm_x2t(bl[ni], uBsl + boff);
            }
#pragma unroll
            for (int mi = 0; mi < 2; mi++)
#pragma unroll
                for (int ni = 0; ni < 4; ni++) {
                    mma_bf16(acc[mi][ni], ah[mi], bh[ni]);
                    mma_bf16(acc[mi][ni], ah[mi], bl[ni]);
                    mma_bf16(acc[mi][ni], al[mi], bh[ni]);
                }
        }
    }

    const int g = lane >> 2;
    const int tig = lane & 3;
#pragma unroll
    for (int mi = 0; mi < 2; mi++) {
        int row0 = m0 + wm * 32 + mi * 16 + g;
        int row1 = row0 + 8;
        float s0 = 1.f, s1 = 1.f;
        if (EPI == 0) {
            if (row0 < M) s0 = g_deg[row0];
            if (row1 < M) s1 = g_deg[row1];
        }
#pragma unroll
        for (int ni = 0; ni < 4; ni++) {
            int col = n0 + wn * 32 + ni * 8 + tig * 2;
            float v0 = acc[mi][ni][0], v1 = acc[mi][ni][1];
            float v2 = acc[mi][ni][2], v3 = acc[mi][ni][3];
            if (EPI == 0) {
                v0 *= s0; v1 *= s0; v2 *= s1; v3 *= s1;
            } else {
                float2 b = *(const float2*)(bias + col);
                v0 += b.x; v1 += b.y; v2 += b.x; v3 += b.y;
                if (EPI == 1) {
                    v0 = fmaxf(v0, 0.f); v1 = fmaxf(v1, 0.f);
                    v2 = fmaxf(v2, 0.f); v3 = fmaxf(v3, 0.f);
                }
            }
            if (row0 < M)
                *(float2*)(C0 + (size_t)row0 * Ncol + col) = make_float2(v0, v1);
            if (row1 < M)
                *(float2*)(C0 + (size_t)row1 * Ncol + col) = make_float2(v2, v3);
        }
    }
}

// ---------------------------------------------------------------------------
// CSR gather: one warp per dst node; acc starts at hprime[d] (self loop).
__global__ void gather_k() {
    int d = blockIdx.x * 8 + (threadIdx.x >> 5);
    int lane = threadIdx.x & 31;
    if (d >= Nn) return;
    const float4* hp = (const float4*)g_hprime;
    float4 acc0 = hp[(size_t)d * 32 + lane];
    float4 acc1 = make_float4(0.f, 0.f, 0.f, 0.f);
    int beg = g_rowptr[d];
    int end = beg + g_cnt[d];
    int e = beg;
    for (; e + 1 < end; e += 2) {
        int s0 = g_esrc[e];
        int s1 = g_esrc[e + 1];
        float4 a = hp[(size_t)s0 * 32 + lane];
        float4 b = hp[(size_t)s1 * 32 + lane];
        acc0.x += a.x; acc0.y += a.y; acc0.z += a.z; acc0.w += a.w;
        acc1.x += b.x; acc1.y += b.y; acc1.z += b.z; acc1.w += b.w;
    }
    if (e < end) {
        int s0 = g_esrc[e];
        float4 a = hp[(size_t)s0 * 32 + lane];
        acc0.x += a.x; acc0.y += a.y; acc0.z += a.z; acc0.w += a.w;
    }
    acc0.x += acc1.x; acc0.y += acc1.y; acc0.z += acc1.z; acc0.w += acc1.w;
    ((float4*)g_agg)[(size_t)d * 32 + lane] = acc0;
}

// ---------------------------------------------------------------------------
__global__ void loss_k(const int* __restrict__ label, const int* __restrict__ m0,
                       const int* __restrict__ m1, const int* __restrict__ m2,
                       float* __restrict__ out) {
    __shared__ float sa[6];
    int tid = threadIdx.x;
    if (tid < 6) sa[tid] = 0.0f;
    __syncthreads();

    int r = blockIdx.x * 8 + (tid >> 5);
    int lane = tid & 31;
    if (r < Nn) {
        const float* row = out + (size_t)r * Cc;
        float x0 = row[lane];
        float x1 = row[lane + 32];
        float* o1 = out + (size_t)Nn * Cc + (size_t)r * Cc;
        float* o2 = o1 + (size_t)Nn * Cc;
        o1[lane] = x0; o1[lane + 32] = x1;
        o2[lane] = x0; o2[lane + 32] = x1;

        float m = fmaxf(x0, x1);
#pragma unroll
        for (int off = 16; off >= 1; off >>= 1)
            m = fmaxf(m, __shfl_xor_sync(0xffffffffu, m, off));
        float se = expf(x0 - m) + expf(x1 - m);
#pragma unroll
        for (int off = 16; off >= 1; off >>= 1)
            se += __shfl_xor_sync(0xffffffffu, se, off);
        float lse = m + logf(se);
        int l = label[r];
        float cand = (l & 32) ? x1 : x0;
        float v = __shfl_sync(0xffffffffu, cand, l & 31);
        float loss = lse - v;
        if (lane == 0) {
            float t0 = (m0[r] == 1) ? 1.0f : 0.0f;
            float t1 = (m1[r] == 1) ? 1.0f : 0.0f;
            float t2 = (m2[r] == 1) ? 1.0f : 0.0f;
            atomicAdd(&sa[0], loss * t0);
            atomicAdd(&sa[1], loss * t1);
            atomicAdd(&sa[2], loss * t2);
            atomicAdd(&sa[3], t0);
            atomicAdd(&sa[4], t1);
            atomicAdd(&sa[5], t2);
        }
    }
    __syncthreads();
    if (tid < 6) atomicAdd(&g_acc[tid], sa[tid]);
}

__global__ void finalize_k(float* __restrict__ out) {
    int k = threadIdx.x;
    if (k < 3) out[(size_t)3 * Nn * Cc + k] = g_acc[k] / g_acc[3 + k];
}

// ---------------------------------------------------------------------------
extern "C" void kernel_launch(void* const* d_in, const int* in_sizes, int n_in,
                              void* d_out, int out_size) {
    const float* feature = (const float*)d_in[0];
    const int* adj       = (const int*)d_in[1];
    const int* label     = (const int*)d_in[2];
    const int* tmask     = (const int*)d_in[3];
    const int* dmask     = (const int*)d_in[4];
    const int* temask    = (const int*)d_in[5];
    const float* W_gcn   = (const float*)d_in[6];
    const float* b_gcn   = (const float*)d_in[7];
    const float* W_ff    = (const float*)d_in[8];
    const float* b_ff    = (const float*)d_in[9];
    const float* W_pred  = (const float*)d_in[10];
    const float* b_pred  = (const float*)d_in[11];
    float* out = (float*)d_out;

    float* d_hprime; cudaGetSymbolAddress((void**)&d_hprime, g_hprime);
    float* d_agg;    cudaGetSymbolAddress((void**)&d_agg, g_agg);
    float* d_hh;     cudaGetSymbolAddress((void**)&d_hh, g_hh);

    const int MB = (Nn + 127) / 128;  // 391

    // 1. CSR build + dinv
    init_k<<<(Nn + 255) / 256, 256>>>();
    cnt_k<<<(Ee + 255) / 256, 256>>>(adj);
    scan1_k<<<NBLK, SCAN_B>>>();
    scan2_k<<<1, 128>>>();
    scan3_k<<<(Nn + 255) / 256, 256>>>();
    fill_k<<<(Ee + 255) / 256, 256>>>(adj);

    // 2. hprime = dinv * (feature @ W_gcn)
    {
        dim3 grid(MB, Ff / 64);
        mmagemm<128, 0, 0><<<grid, 256>>>(feature, W_gcn, nullptr, nullptr,
                                          d_hprime, Nn, Ff);
    }

    // 3. agg[d] = hprime[d] + sum_{s->d} hprime[s]
    gather_k<<<(Nn + 7) / 8, 256>>>();

    // 4+5. hh = relu((dinv*agg + b_gcn) @ W_ff + b_ff)
    {
        dim3 grid(MB, Hh / 64);
        mmagemm<128, 1, 1><<<grid, 256>>>(d_agg, W_ff, b_gcn, b_ff,
                                          d_hh, Nn, Hh);
    }

    // 6. logits = hh @ W_pred + b_pred
    {
        dim3 grid(MB, Cc / 64);
        mmagemm<256, 0, 2><<<grid, 256>>>(d_hh, W_pred, nullptr, b_pred,
                                          out, Nn, Cc);
    }

    // 7. loss + copies + masked sums
    loss_k<<<(Nn + 7) / 8, 256>>>(label, tmask, dmask, temask, out);

    // 8. scalars
    finalize_k<<<1, 32>>>(out);
}

// round 6
// speedup vs baseline: 1.7722x; 1.0167x over previous
#include <cuda_runtime.h>
#include <cuda_bf16.h>
#include <cstdint>

// Problem constants
constexpr int Nn = 50000;
constexpr int Ee = 800000;
constexpr int Ff = 128;
constexpr int Hh = 256;
constexpr int Cc = 64;

constexpr int SCAN_B = 512;
constexpr int NBLK = (Nn + SCAN_B - 1) / SCAN_B;  // 98

// Scratch
__device__ float g_hprime[(size_t)Nn * Ff];
__device__ float g_agg[(size_t)Nn * Ff];
__device__ float g_hh[(size_t)Nn * Hh];
__device__ float g_deg[Nn];     // dinv
__device__ float g_acc[8];
__device__ int g_cnt[Nn];
__device__ int g_fill[Nn];
__device__ int g_rowptr[Nn];    // block-local exclusive scan (needs +bsum[i>>9])
__device__ int g_bsum[128];
__device__ int g_esrc[Ee];

// ---------------------------------------------------------------------------
__global__ void init_k() {
    int i = blockIdx.x * blockDim.x + threadIdx.x;
    if (i < Nn) { g_cnt[i] = 0; g_fill[i] = 0; }
    if (i < 8) g_acc[i] = 0.0f;
}
__global__ void cnt_k(const int* __restrict__ adj) {
    int e = blockIdx.x * blockDim.x + threadIdx.x;
    if (e < Ee) atomicAdd(&g_cnt[adj[Ee + e]], 1);
}
__global__ void scan1_k() {
    __shared__ int s[SCAN_B];
    int tid = threadIdx.x;
    int i = blockIdx.x * SCAN_B + tid;
    int v = (i < Nn) ? g_cnt[i] : 0;
    s[tid] = v;
    __syncthreads();
#pragma unroll
    for (int off = 1; off < SCAN_B; off <<= 1) {
        int t = (tid >= off) ? s[tid - off] : 0;
        __syncthreads();
        s[tid] += t;
        __syncthreads();
    }
    if (i < Nn) {
        g_rowptr[i] = s[tid] - v;
        g_deg[i] = rsqrtf((float)(v + 1));
    }
    if (tid == SCAN_B - 1) g_bsum[blockIdx.x] = s[tid];
}
// exclusive scan of 98 block sums, shfl-based
__global__ void scan2_k() {
    __shared__ int ws[4];
    int tid = threadIdx.x;  // 128
    int v = (tid < NBLK) ? g_bsum[tid] : 0;
    int x = v;
#pragma unroll
    for (int o = 1; o < 32; o <<= 1) {
        int t = __shfl_up_sync(0xffffffffu, x, o);
        if ((tid & 31) >= o) x += t;
    }
    if ((tid & 31) == 31) ws[tid >> 5] = x;
    __syncthreads();
    if (tid == 0) {
        int run = 0;
#pragma unroll
        for (int i = 0; i < 4; i++) { int t = ws[i]; ws[i] = run; run += t; }
    }
    __syncthreads();
    if (tid < NBLK) g_bsum[tid] = x - v + ws[tid >> 5];
}
__global__ void fill_k(const int* __restrict__ adj) {
    int e = blockIdx.x * blockDim.x + threadIdx.x;
    if (e >= Ee) return;
    int src = adj[e];
    int dst = adj[Ee + e];
    int pos = g_rowptr[dst] + g_bsum[dst >> 9] + atomicAdd(&g_fill[dst], 1);
    g_esrc[pos] = src;
}

// ---------------------------------------------------------------------------
__device__ __forceinline__ uint32_t smem_u32(const void* p) {
    uint32_t a;
    asm("{ .reg .u64 t; cvta.to.shared.u64 t, %1; cvt.u32.u64 %0, t; }"
        : "=r"(a) : "l"(p));
    return a;
}
__device__ __forceinline__ void ldsm_x4(uint32_t* r, uint32_t addr) {
    asm volatile("ldmatrix.sync.aligned.m8n8.x4.shared.b16 {%0,%1,%2,%3}, [%4];"
                 : "=r"(r[0]), "=r"(r[1]), "=r"(r[2]), "=r"(r[3]) : "r"(addr));
}
__device__ __forceinline__ void ldsm_x2t(uint32_t* r, uint32_t addr) {
    asm volatile("ldmatrix.sync.aligned.m8n8.x2.trans.shared.b16 {%0,%1}, [%2];"
                 : "=r"(r[0]), "=r"(r[1]) : "r"(addr));
}
__device__ __forceinline__ void mma_bf16(float* d, const uint32_t* a, const uint32_t* b) {
    asm volatile(
        "mma.sync.aligned.m16n8k16.row.col.f32.bf16.bf16.f32 "
        "{%0,%1,%2,%3}, {%4,%5,%6,%7}, {%8,%9}, {%0,%1,%2,%3};"
        : "+f"(d[0]), "+f"(d[1]), "+f"(d[2]), "+f"(d[3])
        : "r"(a[0]), "r"(a[1]), "r"(a[2]), "r"(a[3]), "r"(b[0]), "r"(b[1]));
}
__device__ __forceinline__ void split_bf16(float x, __nv_bfloat16& h, __nv_bfloat16& l) {
    h = __float2bfloat16(x);
    l = __float2bfloat16(x - __bfloat162float(h));
}

// ---------------------------------------------------------------------------
// HMMA bf16-split GEMM, software-pipelined with double-buffered smem.
// BM=128, BN=64, BK=32, 256 threads (8 warps: 4m x 2n), warp tile 32x32.
template <int K, int AXF, int EPI>
__global__ void __launch_bounds__(256)
mmagemm(const float* __restrict__ A, const float* __restrict__ B,
        const float* __restrict__ abias, const float* __restrict__ bias,
        float* __restrict__ C0, int M, int Ncol) {
    constexpr int ASTR = 40;   // bf16 elems per A smem row
    constexpr int BSTR = 72;   // bf16 elems per B smem row
    constexpr int OFF_AL = 128 * ASTR * 2;            // 10240 B
    constexpr int OFF_BH = OFF_AL * 2;                // 20480 B
    constexpr int OFF_BL = OFF_BH + 32 * BSTR * 2;    // 25088 B
    constexpr int STG = OFF_BL + 32 * BSTR * 2;       // 29696 B per stage
    extern __shared__ char smem[];

    const int tid = threadIdx.x;
    const int wid = tid >> 5;
    const int lane = tid & 31;
    const int wm = wid & 3;
    const int wn = wid >> 2;
    const int m0 = blockIdx.x * 128;
    const int n0 = blockIdx.y * 64;

    const uint32_t uS = smem_u32(smem);
    const int l15 = lane & 15;
    const int lh = lane >> 4;
    uint32_t aOff[2];
#pragma unroll
    for (int mi = 0; mi < 2; mi++)
        aOff[mi] = (uint32_t)((wm * 32 + mi * 16 + l15) * (ASTR * 2) + lh * 16);
    const uint32_t bOff = (uint32_t)(l15 * (BSTR * 2) + wn * 64);

    float acc[2][4][4];
#pragma unroll
    for (int mi = 0; mi < 2; mi++)
#pragma unroll
        for (int ni = 0; ni < 4; ni++)
#pragma unroll
            for (int j = 0; j < 4; j++) acc[mi][ni][j] = 0.0f;

    float4 va[4], vb[2];

    auto LD = [&](int c) {
        const int k0 = c * 32;
#pragma unroll
        for (int it = 0; it < 4; it++) {
            int idx = it * 256 + tid;
            int r = idx >> 3, q = idx & 7;
            int gr = m0 + r;
            float4 v = make_float4(0.f, 0.f, 0.f, 0.f);
            if (gr < M) {
                v = *(const float4*)(A + (size_t)gr * K + k0 + q * 4);
                if (AXF) {
                    float sc = g_deg[gr];
                    float4 bb = *(const float4*)(abias + k0 + q * 4);
                    v.x = sc * v.x + bb.x; v.y = sc * v.y + bb.y;
                    v.z = sc * v.z + bb.z; v.w = sc * v.w + bb.w;
                }
            }
            va[it] = v;
        }
#pragma unroll
        for (int it = 0; it < 2; it++) {
            int idx = it * 256 + tid;
            int kk = idx >> 4, n4 = (idx & 15) * 4;
            vb[it] = *(const float4*)(B + (size_t)(k0 + kk) * Ncol + n0 + n4);
        }
    };
    auto ST = [&](int st) {
        char* tile = smem + st * STG;
#pragma unroll
        for (int it = 0; it < 4; it++) {
            int idx = it * 256 + tid;
            int r = idx >> 3, q = idx & 7;
            float4 v = va[it];
            __nv_bfloat16 hx, lx, hy, ly, hz, lz, hw, lw;
            split_bf16(v.x, hx, lx); split_bf16(v.y, hy, ly);
            split_bf16(v.z, hz, lz); split_bf16(v.w, hw, lw);
            int e = (r * ASTR + q * 4) * 2;
            *(__nv_bfloat162*)(tile + e)              = __nv_bfloat162(hx, hy);
            *(__nv_bfloat162*)(tile + e + 4)          = __nv_bfloat162(hz, hw);
            *(__nv_bfloat162*)(tile + OFF_AL + e)     = __nv_bfloat162(lx, ly);
            *(__nv_bfloat162*)(tile + OFF_AL + e + 4) = __nv_bfloat162(lz, lw);
        }
#pragma unroll
        for (int it = 0; it < 2; it++) {
            int idx = it * 256 + tid;
            int kk = idx >> 4, n4 = (idx & 15) * 4;
            float4 v = vb[it];
            __nv_bfloat16 hx, lx, hy, ly, hz, lz, hw, lw;
            split_bf16(v.x, hx, lx); split_bf16(v.y, hy, ly);
            split_bf16(v.z, hz, lz); split_bf16(v.w, hw, lw);
            int e = (kk * BSTR + n4) * 2;
            *(__nv_bfloat162*)(tile + OFF_BH + e)     = __nv_bfloat162(hx, hy);
            *(__nv_bfloat162*)(tile + OFF_BH + e + 4) = __nv_bfloat162(hz, hw);
            *(__nv_bfloat162*)(tile + OFF_BL + e)     = __nv_bfloat162(lx, ly);
            *(__nv_bfloat162*)(tile + OFF_BL + e + 4) = __nv_bfloat162(lz, lw);
        }
    };
    auto CMP = [&](int st) {
        uint32_t base = uS + st * STG;
#pragma unroll
        for (int ks = 0; ks < 2; ks++) {
            uint32_t ah[2][4], al[2][4], bh[4][2], bl[4][2];
#pragma unroll
            for (int mi = 0; mi < 2; mi++) {
                ldsm_x4(ah[mi], base + aOff[mi] + ks * 32);
                ldsm_x4(al[mi], base + OFF_AL + aOff[mi] + ks * 32);
            }
#pragma unroll
            for (int ni = 0; ni < 4; ni++) {
                uint32_t bo = bOff + ks * 16 * (BSTR * 2) + ni * 16;
                ldsm_x2t(bh[ni], base + OFF_BH + bo);
                ldsm_x2t(bl[ni], base + OFF_BL + bo);
            }
#pragma unroll
            for (int mi = 0; mi < 2; mi++)
#pragma unroll
                for (int ni = 0; ni < 4; ni++) {
                    mma_bf16(acc[mi][ni], ah[mi], bh[ni]);
                    mma_bf16(acc[mi][ni], ah[mi], bl[ni]);
                    mma_bf16(acc[mi][ni], al[mi], bh[ni]);
                }
        }
    };

    constexpr int NC = K / 32;
    LD(0);
    ST(0);
    __syncthreads();
#pragma unroll 1
    for (int c = 0; c < NC; c++) {
        if (c + 1 < NC) LD(c + 1);       // issue global loads
        CMP(c & 1);                       // HMMA hides LDG latency
        if (c + 1 < NC) ST((c + 1) & 1);  // convert + STS into free buffer
        __syncthreads();
    }

    // ---- epilogue ----
    const int g = lane >> 2;
    const int tig = lane & 3;
#pragma unroll
    for (int mi = 0; mi < 2; mi++) {
        int row0 = m0 + wm * 32 + mi * 16 + g;
        int row1 = row0 + 8;
        float s0 = 1.f, s1 = 1.f;
        if (EPI == 0) {
            if (row0 < M) s0 = g_deg[row0];
            if (row1 < M) s1 = g_deg[row1];
        }
#pragma unroll
        for (int ni = 0; ni < 4; ni++) {
            int col = n0 + wn * 32 + ni * 8 + tig * 2;
            float v0 = acc[mi][ni][0], v1 = acc[mi][ni][1];
            float v2 = acc[mi][ni][2], v3 = acc[mi][ni][3];
            if (EPI == 0) {
                v0 *= s0; v1 *= s0; v2 *= s1; v3 *= s1;
            } else {
                float2 b = *(const float2*)(bias + col);
                v0 += b.x; v1 += b.y; v2 += b.x; v3 += b.y;
                if (EPI == 1) {
                    v0 = fmaxf(v0, 0.f); v1 = fmaxf(v1, 0.f);
                    v2 = fmaxf(v2, 0.f); v3 = fmaxf(v3, 0.f);
                }
            }
            if (row0 < M)
                *(float2*)(C0 + (size_t)row0 * Ncol + col) = make_float2(v0, v1);
            if (row1 < M)
                *(float2*)(C0 + (size_t)row1 * Ncol + col) = make_float2(v2, v3);
        }
    }
}

// ---------------------------------------------------------------------------
// CSR gather, 4-way unrolled: agg[d] = hprime[d] + sum hprime[src]
__global__ void gather_k() {
    int d = blockIdx.x * 8 + (threadIdx.x >> 5);
    int lane = threadIdx.x & 31;
    if (d >= Nn) return;
    const float4* hp = (const float4*)g_hprime;
    float4 a0 = hp[(size_t)d * 32 + lane];
    float4 a1 = make_float4(0.f, 0.f, 0.f, 0.f);
    float4 a2 = make_float4(0.f, 0.f, 0.f, 0.f);
    float4 a3 = make_float4(0.f, 0.f, 0.f, 0.f);
    int beg = g_rowptr[d] + g_bsum[d >> 9];
    int end = beg + g_cnt[d];
    int e = beg;
    for (; e + 3 < end; e += 4) {
        int s0 = g_esrc[e], s1 = g_esrc[e + 1], s2 = g_esrc[e + 2], s3 = g_esrc[e + 3];
        float4 v0 = hp[(size_t)s0 * 32 + lane];
        float4 v1 = hp[(size_t)s1 * 32 + lane];
        float4 v2 = hp[(size_t)s2 * 32 + lane];
        float4 v3 = hp[(size_t)s3 * 32 + lane];
        a0.x += v0.x; a0.y += v0.y; a0.z += v0.z; a0.w += v0.w;
        a1.x += v1.x; a1.y += v1.y; a1.z += v1.z; a1.w += v1.w;
        a2.x += v2.x; a2.y += v2.y; a2.z += v2.z; a2.w += v2.w;
        a3.x += v3.x; a3.y += v3.y; a3.z += v3.z; a3.w += v3.w;
    }
    for (; e < end; e++) {
        int s0 = g_esrc[e];
        float4 v0 = hp[(size_t)s0 * 32 + lane];
        a0.x += v0.x; a0.y += v0.y; a0.z += v0.z; a0.w += v0.w;
    }
    a0.x += a1.x + a2.x + a3.x;
    a0.y += a1.y + a2.y + a3.y;
    a0.z += a1.z + a2.z + a3.z;
    a0.w += a1.w + a2.w + a3.w;
    ((float4*)g_agg)[(size_t)d * 32 + lane] = a0;
}

// ---------------------------------------------------------------------------
__global__ void loss_k(const int* __restrict__ label, const int* __restrict__ m0,
                       const int* __restrict__ m1, const int* __restrict__ m2,
                       float* __restrict__ out) {
    __shared__ float sa[6];
    int tid = threadIdx.x;
    if (tid < 6) sa[tid] = 0.0f;
    __syncthreads();

    int r = blockIdx.x * 8 + (tid >> 5);
    int lane = tid & 31;
    if (r < Nn) {
        const float* row = out + (size_t)r * Cc;
        float x0 = row[lane];
        float x1 = row[lane + 32];
        float* o1 = out + (size_t)Nn * Cc + (size_t)r * Cc;
        float* o2 = o1 + (size_t)Nn * Cc;
        o1[lane] = x0; o1[lane + 32] = x1;
        o2[lane] = x0; o2[lane + 32] = x1;

        float m = fmaxf(x0, x1);
#pragma unroll
        for (int off = 16; off >= 1; off >>= 1)
            m = fmaxf(m, __shfl_xor_sync(0xffffffffu, m, off));
        float se = expf(x0 - m) + expf(x1 - m);
#pragma unroll
        for (int off = 16; off >= 1; off >>= 1)
            se += __shfl_xor_sync(0xffffffffu, se, off);
        float lse = m + logf(se);
        int l = label[r];
        float cand = (l & 32) ? x1 : x0;
        float v = __shfl_sync(0xffffffffu, cand, l & 31);
        float loss = lse - v;
        if (lane == 0) {
            float t0 = (m0[r] == 1) ? 1.0f : 0.0f;
            float t1 = (m1[r] == 1) ? 1.0f : 0.0f;
            float t2 = (m2[r] == 1) ? 1.0f : 0.0f;
            atomicAdd(&sa[0], loss * t0);
            atomicAdd(&sa[1], loss * t1);
            atomicAdd(&sa[2], loss * t2);
            atomicAdd(&sa[3], t0);
            atomicAdd(&sa[4], t1);
            atomicAdd(&sa[5], t2);
        }
    }
    __syncthreads();
    if (tid < 6) atomicAdd(&g_acc[tid], sa[tid]);
}

__global__ void finalize_k(float* __restrict__ out) {
    int k = threadIdx.x;
    if (k < 3) out[(size_t)3 * Nn * Cc + k] = g_acc[k] / g_acc[3 + k];
}

// ---------------------------------------------------------------------------
extern "C" void kernel_launch(void* const* d_in, const int* in_sizes, int n_in,
                              void* d_out, int out_size) {
    const float* feature = (const float*)d_in[0];
    const int* adj       = (const int*)d_in[1];
    const int* label     = (const int*)d_in[2];
    const int* tmask     = (const int*)d_in[3];
    const int* dmask     = (const int*)d_in[4];
    const int* temask    = (const int*)d_in[5];
    const float* W_gcn   = (const float*)d_in[6];
    const float* b_gcn   = (const float*)d_in[7];
    const float* W_ff    = (const float*)d_in[8];
    const float* b_ff    = (const float*)d_in[9];
    const float* W_pred  = (const float*)d_in[10];
    const float* b_pred  = (const float*)d_in[11];
    float* out = (float*)d_out;

    float* d_hprime; cudaGetSymbolAddress((void**)&d_hprime, g_hprime);
    float* d_agg;    cudaGetSymbolAddress((void**)&d_agg, g_agg);
    float* d_hh;     cudaGetSymbolAddress((void**)&d_hh, g_hh);

    const int MB = (Nn + 127) / 128;  // 391
    const int SMEM_DYN = 59392;       // 2 stages x 29696 B

    static int attr_done = 0;
    if (!attr_done) {
        cudaFuncSetAttribute(mmagemm<128, 0, 0>, cudaFuncAttributeMaxDynamicSharedMemorySize, SMEM_DYN);
        cudaFuncSetAttribute(mmagemm<128, 1, 1>, cudaFuncAttributeMaxDynamicSharedMemorySize, SMEM_DYN);
        cudaFuncSetAttribute(mmagemm<256, 0, 2>, cudaFuncAttributeMaxDynamicSharedMemorySize, SMEM_DYN);
        attr_done = 1;
    }

    // 1. CSR build + dinv
    init_k<<<(Nn + 255) / 256, 256>>>();
    cnt_k<<<(Ee + 255) / 256, 256>>>(adj);
    scan1_k<<<NBLK, SCAN_B>>>();
    scan2_k<<<1, 128>>>();
    fill_k<<<(Ee + 255) / 256, 256>>>(adj);

    // 2. hprime = dinv * (feature @ W_gcn)
    {
        dim3 grid(MB, Ff / 64);
        mmagemm<128, 0, 0><<<grid, 256, SMEM_DYN>>>(feature, W_gcn, nullptr, nullptr,
                                                    d_hprime, Nn, Ff);
    }

    // 3. agg[d] = hprime[d] + sum_{s->d} hprime[s]
    gather_k<<<(Nn + 7) / 8, 256>>>();

    // 4+5. hh = relu((dinv*agg + b_gcn) @ W_ff + b_ff)
    {
        dim3 grid(MB, Hh / 64);
        mmagemm<128, 1, 1><<<grid, 256, SMEM_DYN>>>(d_agg, W_ff, b_gcn, b_ff,
                                                    d_hh, Nn, Hh);
    }

    // 6. logits = hh @ W_pred + b_pred
    {
        dim3 grid(MB, Cc / 64);
        mmagemm<256, 0, 2><<<grid, 256, SMEM_DYN>>>(d_hh, W_pred, nullptr, b_pred,
                                                    out, Nn, Cc);
    }

    // 7. loss + copies + masked sums
    loss_k<<<(Nn + 7) / 8, 256>>>(label, tmask, dmask, temask, out);

    // 8. scalars
    finalize_k<<<1, 32>>>(out);
}